// round 5
// baseline (speedup 1.0000x reference)
#include <cuda_runtime.h>
#include <math.h>
#include <stdint.h>
#include <stddef.h>

#define BB 16
#define TT 2048
#define HH 768
#define G4 3072
#define NH 12
#define HD 64

// ---------------- recurrent kernel config ----------------
#define RGRID 128
#define RC 6                  // hidden units per block
#define RROWS 24              // 4 gates * RC
#define RTHREADS 128
#define SLICES 16             // k-split
#define SLICE_K 48            // k per slice
#define SLICE_P 52            // padded slice pitch (floats); 13 f4, odd -> conflict-free
#define ROWP (SLICES * SLICE_P)   // 832 floats: pitch for ws rows and hs batches
#define PRP 385               // partial array slice pitch (floats), odd -> conflict-free
#define RECUR_SMEM_FLOATS (RROWS*ROWP + BB*ROWP + SLICES*PRP + 32)
#define RECUR_SMEM_BYTES (RECUR_SMEM_FLOATS * 4)

// ---------------- projection kernel config ----------------
#define PGT 256               // g rows per block
#define PKC 32                // k chunk
#define PTHREADS 128
#define PCHUNKS (HH / PKC)    // 24
#define PROJ_SMEM_FLOATS (BB*772 + 2*PGT*PKC)
#define PROJ_SMEM_BYTES (PROJ_SMEM_FLOATS * 4)

// ---------------- global scratch ----------------
__device__ float g_xg[(size_t)TT * G4 * BB];   // [t][g][b]  ~403 MB
__device__ float g_h[2][BB * HH];              // [buf][b][k]
__device__ unsigned g_flags[RGRID];            // per-CTA step flags

// ---------------- packed fp32x2 FMA helpers ----------------
__device__ __forceinline__ unsigned long long ffma2(unsigned long long a,
                                                    unsigned long long b,
                                                    unsigned long long c) {
    unsigned long long d;
    asm("fma.rn.f32x2 %0, %1, %2, %3;" : "=l"(d) : "l"(a), "l"(b), "l"(c));
    return d;
}
__device__ __forceinline__ float2 unpack2(unsigned long long v) {
    float2 r;
    asm("mov.b64 {%0, %1}, %2;" : "=f"(r.x), "=f"(r.y) : "l"(v));
    return r;
}

// =======================================================================
// projection: xg[t][g][b] = sum_d W_ih[g][d]*x[b][t][d] + b_ih[g] + b_hh[g]
// CTA tile: 256 g x 16 b x 768 k; thread tile 8g x 4b (strided b).
// grid: (12, 2048), 128 threads. Block (0,0) also zero-inits h/flags.
// =======================================================================
__global__ void __launch_bounds__(PTHREADS)
proj_kernel(const float* __restrict__ state,
            const float* __restrict__ W_ih,
            const float* __restrict__ b_ih,
            const float* __restrict__ b_hh) {
    extern __shared__ float smem[];
    float4* xs4  = (float4*)smem;                 // [16][193] f4
    float4* wbuf = (float4*)(smem + BB * 772);    // 2 * 2048 f4, swizzled

    const int t   = blockIdx.y;
    const int g0  = blockIdx.x * PGT;
    const int tid = threadIdx.x;

    if (blockIdx.x == 0 && blockIdx.y == 0) {
        for (int i = tid; i < BB * HH; i += PTHREADS) g_h[0][i] = 0.0f;
        if (tid < RGRID) g_flags[tid] = 0u;
    }

    // load x slice for this t
    const float4* st4 = (const float4*)state;
    #pragma unroll 4
    for (int fi = tid; fi < BB * 192; fi += PTHREADS) {
        int b  = fi / 192;
        int d4 = fi % 192;
        int head = d4 >> 4;
        int dl   = d4 & 15;
        xs4[b * 193 + d4] = st4[(((size_t)(b * NH + head)) * TT + t) * 16 + dl];
    }

    // prefetch weight chunk 0 (swizzle: c4 ^ (row>>3 & 7))
    const float4* w4 = (const float4*)W_ih;
    #pragma unroll 4
    for (int idx = tid; idx < PGT * 8; idx += PTHREADS) {
        int row = idx >> 3, c4 = idx & 7;
        wbuf[row * 8 + (c4 ^ ((row >> 3) & 7))] = w4[(size_t)(g0 + row) * 192 + c4];
    }

    const int tb = tid & 3;          // b = tb + 4j (strided)
    const int tg = tid >> 2;         // 0..31 : rows 8tg..8tg+7
    unsigned long long acc[8][4];
    #pragma unroll
    for (int i = 0; i < 8; i++)
        #pragma unroll
        for (int j = 0; j < 4; j++) acc[i][j] = 0ull;

    int buf = 0;
    for (int c = 0; c < PCHUNKS; ++c) {
        __syncthreads();
        if (c + 1 < PCHUNKS) {
            int nb = buf ^ 1;
            #pragma unroll 4
            for (int idx = tid; idx < PGT * 8; idx += PTHREADS) {
                int row = idx >> 3, c4 = idx & 7;
                wbuf[nb * 2048 + row * 8 + (c4 ^ ((row >> 3) & 7))] =
                    w4[(size_t)(g0 + row) * 192 + (c + 1) * 8 + c4];
            }
        }
        const float4* wb = wbuf + buf * 2048;
        #pragma unroll
        for (int c4 = 0; c4 < 8; ++c4) {
            ulonglong2 wv[8];
            #pragma unroll
            for (int i = 0; i < 8; i++)
                wv[i] = *(const ulonglong2*)(wb + (8 * tg + i) * 8 + (c4 ^ (tg & 7)));
            ulonglong2 xv[4];
            #pragma unroll
            for (int j = 0; j < 4; j++)
                xv[j] = *(const ulonglong2*)(xs4 + (tb + 4 * j) * 193 + c * 8 + c4);
            #pragma unroll
            for (int i = 0; i < 8; i++) {
                #pragma unroll
                for (int j = 0; j < 4; j++) {
                    acc[i][j] = ffma2(wv[i].x, xv[j].x, acc[i][j]);
                    acc[i][j] = ffma2(wv[i].y, xv[j].y, acc[i][j]);
                }
            }
        }
        buf ^= 1;
    }

    // store: 8 rows x 4 strided b, scalar
    #pragma unroll
    for (int i = 0; i < 8; i++) {
        int g = g0 + 8 * tg + i;
        float bias = b_ih[g] + b_hh[g];
        size_t base = ((size_t)t * G4 + g) * BB;
        #pragma unroll
        for (int j = 0; j < 4; j++) {
            float2 p = unpack2(acc[i][j]);
            __stcs(&g_xg[base + (tb + 4 * j)], p.x + p.y + bias);
        }
    }
}

// =======================================================================
// recurrence: 128 persistent CTAs, 24 rows each.
// warp = gate (6 rows); lane = (batch-half j, k-slice s of 48 k).
// Thread tile: 6 rows x 8 batches x 48 k. 16-way k-split reduced in smem.
// =======================================================================
__global__ void __launch_bounds__(RTHREADS)
recur_kernel(const float* __restrict__ W_hh, float* __restrict__ out) {
    extern __shared__ float smem[];
    float* ws = smem;                          // [24][ROWP]
    float* hs = smem + RROWS * ROWP;           // [16][ROWP]
    float* pr = hs + BB * ROWP;                // [16 slices][PRP]

    const int blk  = blockIdx.x;
    const int tid  = threadIdx.x;
    const int lane = tid & 31;
    const int wrp  = tid >> 5;                 // gate / row-group
    const int s    = lane & 15;                // k-slice
    const int j    = lane >> 4;                // batch half

    // load 24 W_hh rows into sliced layout: ws[r][sl*52 + kk]
    const float4* wh4 = (const float4*)W_hh;
    #pragma unroll 4
    for (int idx = tid; idx < RROWS * 192; idx += RTHREADS) {
        int r  = idx / 192, f4 = idx % 192;
        int gr = (r / RC) * HH + blk * RC + (r % RC);
        int sl = f4 / 12, kk = f4 % 12;
        *(float4*)(ws + r * ROWP + sl * SLICE_P + kk * 4) = wh4[(size_t)gr * 192 + f4];
    }

    // cell threads (tid < 96)
    const int eb = tid & 15;
    const int eu = tid >> 4;
    float cstate = 0.0f;

    volatile unsigned* vflags = (volatile unsigned*)g_flags;

    __syncthreads();

    for (int t = 0; t < TT; ++t) {
        // prefetch xg gate contributions (in flight across the barrier)
        float a[4];
        if (tid < 96) {
            const size_t xoff = (size_t)t * G4 * BB;
            #pragma unroll
            for (int q = 0; q < 4; ++q)
                a[q] = __ldcs(&g_xg[xoff + (size_t)(q * HH + blk * RC + eu) * BB + eb]);
        }

        // global barrier
        if (t > 0) {
            unsigned tgt = (unsigned)t;
            while (vflags[tid] < tgt) { }
            __threadfence();
        }
        __syncthreads();

        // stage h(t-1): warp w stages batches 4w..4w+3 into sliced layout
        const int pb = t & 1;
        {
            const float4* src = (const float4*)g_h[pb];   // [b][192 f4]
            #pragma unroll
            for (int pass = 0; pass < 2; ++pass) {
                float4 tmp[12];
                #pragma unroll
                for (int i = 0; i < 12; ++i) {
                    int idx = pass * 384 + i * 32 + lane;  // 0..767
                    int bl = idx / 192, f4 = idx % 192;
                    tmp[i] = __ldcg(src + (4 * wrp + bl) * 192 + f4);
                }
                #pragma unroll
                for (int i = 0; i < 12; ++i) {
                    int idx = pass * 384 + i * 32 + lane;
                    int bl = idx / 192, f4 = idx % 192;
                    int sl = f4 / 12, kk = f4 % 12;
                    *(float4*)(hs + (4 * wrp + bl) * ROWP + sl * SLICE_P + kk * 4) = tmp[i];
                }
            }
        }
        __syncthreads();

        // GEMV: 6 rows x 8 batches x 48 k per thread (packed FFMA2)
        unsigned long long acc[6][8];
        #pragma unroll
        for (int i = 0; i < 6; i++)
            #pragma unroll
            for (int m = 0; m < 8; m++) acc[i][m] = 0ull;

        const float* wbase = ws + (6 * wrp) * ROWP + s * SLICE_P;
        const float* hbase = hs + (8 * j) * ROWP + s * SLICE_P;
        #pragma unroll 4
        for (int k4 = 0; k4 < 12; ++k4) {
            ulonglong2 wv[6];
            #pragma unroll
            for (int i = 0; i < 6; i++)
                wv[i] = *(const ulonglong2*)(wbase + i * ROWP + 4 * k4);
            ulonglong2 hv[8];
            #pragma unroll
            for (int m = 0; m < 8; m++)
                hv[m] = *(const ulonglong2*)(hbase + m * ROWP + 4 * k4);
            #pragma unroll
            for (int i = 0; i < 6; i++) {
                #pragma unroll
                for (int m = 0; m < 8; m++) {
                    acc[i][m] = ffma2(wv[i].x, hv[m].x, acc[i][m]);
                    acc[i][m] = ffma2(wv[i].y, hv[m].y, acc[i][m]);
                }
            }
        }

        // partials: pr[s][row*16 + b]
        #pragma unroll
        for (int i = 0; i < 6; i++) {
            #pragma unroll
            for (int m = 0; m < 8; m++) {
                float2 p = unpack2(acc[i][m]);
                pr[s * PRP + (6 * wrp + i) * BB + (8 * j + m)] = p.x + p.y;
            }
        }
        __syncthreads();

        // reduce 16 slices + cell (96 threads)
        if (tid < 96) {
            float gs[4];
            #pragma unroll
            for (int q = 0; q < 4; ++q) {
                float sum = a[q];
                int ro = (q * RC + eu) * BB + eb;
                #pragma unroll
                for (int ss = 0; ss < 16; ++ss) sum += pr[ss * PRP + ro];
                gs[q] = sum;
            }
            float gi = __fdividef(1.0f, 1.0f + __expf(-gs[0]));
            float gf = __fdividef(1.0f, 1.0f + __expf(-gs[1]));
            float gc = __fdividef(2.0f, 1.0f + __expf(-2.0f * gs[2])) - 1.0f;
            float go = __fdividef(1.0f, 1.0f + __expf(-gs[3]));
            cstate = gf * cstate + gi * gc;
            float th = __fdividef(2.0f, 1.0f + __expf(-2.0f * cstate)) - 1.0f;
            float hv = go * th;
            int hid = blk * RC + eu;
            __stcg(&g_h[pb ^ 1][eb * HH + hid], hv);
            __stcs(&out[(((size_t)(eb * NH + (hid >> 6))) * TT + t) * HD + (hid & 63)], hv);
        }
        __syncthreads();

        if (tid == 0) {
            __threadfence();
            atomicExch(&g_flags[blk], (unsigned)(t + 1));
        }
    }
}

// =======================================================================
extern "C" void kernel_launch(void* const* d_in, const int* in_sizes, int n_in,
                              void* d_out, int out_size) {
    const float* state = (const float*)d_in[0];
    const float* W_ih  = (const float*)d_in[1];
    const float* W_hh  = (const float*)d_in[2];
    const float* b_ih  = (const float*)d_in[3];
    const float* b_hh  = (const float*)d_in[4];
    float* out = (float*)d_out;

    cudaFuncSetAttribute(proj_kernel,  cudaFuncAttributeMaxDynamicSharedMemorySize, PROJ_SMEM_BYTES);
    cudaFuncSetAttribute(recur_kernel, cudaFuncAttributeMaxDynamicSharedMemorySize, RECUR_SMEM_BYTES);

    dim3 pgrid(G4 / PGT, TT);   // (12, 2048)
    proj_kernel<<<pgrid, PTHREADS, PROJ_SMEM_BYTES>>>(state, W_ih, b_ih, b_hh);

    recur_kernel<<<RGRID, RTHREADS, RECUR_SMEM_BYTES>>>(W_hh, out);
}